// round 1
// baseline (speedup 1.0000x reference)
#include <cuda_runtime.h>
#include <math.h>

// Problem constants
#define BB      16
#define NSEQ    1024
#define CC      768
#define HH      12
#define HDD     64
#define MTOK    (BB * NSEQ)      // 16384
#define QKVN    (3 * CC)         // 2304

// Scratch (static device globals; no allocation at runtime)
__device__ float g_qkv[(size_t)MTOK * QKVN];                    // [B*N, 3C]
__device__ float g_scores[(size_t)BB * HH * NSEQ * NSEQ];       // [B,H,N,N]
__device__ float g_attn[(size_t)MTOK * CC];                     // [B,N,C] (H,HD interleaved)

// ---------------------------------------------------------------------------
// Generic tiled SGEMM.
//   C[z] = alpha * A[z] * op(B[z]) (+ bias)
//   op(B) = B          if !TRANSB  (B is [K, N] row-major, ldb)
//   op(B) = B^T        if  TRANSB  (B is [N, K] row-major, ldb)
// Batch index z = blockIdx.z decomposed as zo = z / binner, zi = z % binner,
// with per-operand offsets zo*s?o + zi*s?i (handles the [B][H] double batch).
// All dimensions must divide the tile sizes exactly (true for every use here).
// ---------------------------------------------------------------------------
template<int BM, int BN, int BK, int TM, int TN, bool TRANSB, bool BIAS>
__global__ void gemm_kernel(const float* __restrict__ A,
                            const float* __restrict__ B,
                            const float* __restrict__ bias,
                            float* __restrict__ C,
                            int M, int Nn, int K,
                            int lda, int ldb, int ldc,
                            int binner,
                            long long sAo, long long sAi,
                            long long sBo, long long sBi,
                            long long sCo, long long sCi,
                            float alpha)
{
    constexpr int THREADS = (BM / TM) * (BN / TN);
    const int tid = threadIdx.x;
    const int tx  = tid % (BN / TN);
    const int ty  = tid / (BN / TN);

    const int z  = blockIdx.z;
    const int zo = z / binner;
    const int zi = z % binner;
    A += zo * sAo + zi * sAi;
    B += zo * sBo + zi * sBi;
    C += zo * sCo + zi * sCi;

    const int bn0 = blockIdx.x * BN;
    const int bm0 = blockIdx.y * BM;

    __shared__ float As[BK][BM + 1];
    __shared__ float Bs[BK][BN + 1];

    float acc[TM][TN];
#pragma unroll
    for (int i = 0; i < TM; i++)
#pragma unroll
        for (int j = 0; j < TN; j++)
            acc[i][j] = 0.0f;

    for (int k0 = 0; k0 < K; k0 += BK) {
        // --- load A tile (BM x BK), store transposed into As[k][m]
#pragma unroll
        for (int it = 0; it < (BM * BK) / THREADS; it++) {
            int idx = tid + it * THREADS;
            int r = idx / BK;
            int c = idx % BK;
            As[c][r] = A[(size_t)(bm0 + r) * lda + (k0 + c)];
        }
        // --- load B tile (BK x BN)
        if (!TRANSB) {
#pragma unroll
            for (int it = 0; it < (BK * BN) / THREADS; it++) {
                int idx = tid + it * THREADS;
                int r = idx / BN;
                int c = idx % BN;
                Bs[r][c] = B[(size_t)(k0 + r) * ldb + (bn0 + c)];
            }
        } else {
#pragma unroll
            for (int it = 0; it < (BK * BN) / THREADS; it++) {
                int idx = tid + it * THREADS;
                int n = idx / BK;
                int k = idx % BK;
                Bs[k][n] = B[(size_t)(bn0 + n) * ldb + (k0 + k)];
            }
        }
        __syncthreads();

#pragma unroll
        for (int kk = 0; kk < BK; kk++) {
            float a[TM], b[TN];
#pragma unroll
            for (int i = 0; i < TM; i++) a[i] = As[kk][ty * TM + i];
#pragma unroll
            for (int j = 0; j < TN; j++) b[j] = Bs[kk][tx * TN + j];
#pragma unroll
            for (int i = 0; i < TM; i++)
#pragma unroll
                for (int j = 0; j < TN; j++)
                    acc[i][j] = fmaf(a[i], b[j], acc[i][j]);
        }
        __syncthreads();
    }

    // --- epilogue
#pragma unroll
    for (int i = 0; i < TM; i++) {
        int row = bm0 + ty * TM + i;
#pragma unroll
        for (int j = 0; j < TN; j++) {
            int col = bn0 + tx * TN + j;
            float v = acc[i][j] * alpha;
            if (BIAS) v += bias[col];
            C[(size_t)row * ldc + col] = v;
        }
    }
}

// ---------------------------------------------------------------------------
// Row softmax over rows of length 1024 (one block = one row, 256 threads).
// ---------------------------------------------------------------------------
__global__ void softmax_kernel(float* __restrict__ S)
{
    const int n = NSEQ;               // 1024
    const int T = 256;                // blockDim.x
    float* row = S + (size_t)blockIdx.x * n;
    const int tid  = threadIdx.x;
    const int lane = tid & 31;
    const int wid  = tid >> 5;

    float v[4];
    float vmax = -3.4e38f;
#pragma unroll
    for (int i = 0; i < 4; i++) {
        v[i] = row[tid + i * T];
        vmax = fmaxf(vmax, v[i]);
    }
#pragma unroll
    for (int o = 16; o > 0; o >>= 1)
        vmax = fmaxf(vmax, __shfl_xor_sync(0xffffffffu, vmax, o));

    __shared__ float smax[8];
    __shared__ float ssum[8];
    if (lane == 0) smax[wid] = vmax;
    __syncthreads();
    float m = smax[0];
#pragma unroll
    for (int i = 1; i < 8; i++) m = fmaxf(m, smax[i]);

    float s = 0.0f;
#pragma unroll
    for (int i = 0; i < 4; i++) {
        v[i] = __expf(v[i] - m);
        s += v[i];
    }
#pragma unroll
    for (int o = 16; o > 0; o >>= 1)
        s += __shfl_xor_sync(0xffffffffu, s, o);
    if (lane == 0) ssum[wid] = s;
    __syncthreads();
    float tot = 0.0f;
#pragma unroll
    for (int i = 0; i < 8; i++) tot += ssum[i];

    float inv = 1.0f / tot;
#pragma unroll
    for (int i = 0; i < 4; i++)
        row[tid + i * T] = v[i] * inv;
}

// ---------------------------------------------------------------------------
// Launch
// ---------------------------------------------------------------------------
extern "C" void kernel_launch(void* const* d_in, const int* in_sizes, int n_in,
                              void* d_out, int out_size)
{
    const float* x    = (const float*)d_in[0];   // [B,N,C]
    const float* Wqkv = (const float*)d_in[1];   // [C, 3C]
    const float* bqkv = (const float*)d_in[2];   // [3C]
    const float* Wout = (const float*)d_in[3];   // [C, C]
    const float* bout = (const float*)d_in[4];   // [C]
    float* out = (float*)d_out;                  // [B,N,C]

    float *qkv = nullptr, *scores = nullptr, *attn = nullptr;
    cudaGetSymbolAddress((void**)&qkv,    g_qkv);
    cudaGetSymbolAddress((void**)&scores, g_scores);
    cudaGetSymbolAddress((void**)&attn,   g_attn);

    const float scale = 1.0f / 8.0f;   // 1/sqrt(HD=64)

    // 1) QKV projection: [16384,768] @ [768,2304] + bias -> qkv [16384,2304]
    gemm_kernel<128,128,16,8,8,false,true>
        <<<dim3(QKVN/128, MTOK/128, 1), 256>>>(
            x, Wqkv, bqkv, qkv,
            MTOK, QKVN, CC,
            CC, QKVN, QKVN,
            1, 0,0, 0,0, 0,0, 1.0f);

    // 2) scores[b,h] = (Q K^T) * scale : batched NT GEMM, 1024x1024x64, 192 batches
    gemm_kernel<128,128,16,8,8,true,false>
        <<<dim3(NSEQ/128, NSEQ/128, BB*HH), 256>>>(
            qkv /* Q cols 0..767 */, qkv + CC /* K */, nullptr, scores,
            NSEQ, NSEQ, HDD,
            QKVN, QKVN, NSEQ,
            HH,
            (long long)NSEQ * QKVN, (long long)HDD,      // A: b-stride, h-stride
            (long long)NSEQ * QKVN, (long long)HDD,      // B
            (long long)HH * NSEQ * NSEQ, (long long)NSEQ * NSEQ,  // C
            scale);

    // 3) softmax over last dim, one block per row
    softmax_kernel<<<BB * HH * NSEQ, 256>>>(scores);

    // 4) attn[b,h] = P @ V : batched NN GEMM, 1024x64x1024, into [B,N,H*HD]
    gemm_kernel<128,64,16,8,4,false,false>
        <<<dim3(1, NSEQ/128, BB*HH), 256>>>(
            scores, qkv + 2*CC /* V */, nullptr, attn,
            NSEQ, HDD, NSEQ,
            NSEQ, QKVN, CC,
            HH,
            (long long)HH * NSEQ * NSEQ, (long long)NSEQ * NSEQ,  // A
            (long long)NSEQ * QKVN, (long long)HDD,               // B
            (long long)NSEQ * CC, (long long)HDD,                 // C
            1.0f);

    // 5) output projection: [16384,768] @ [768,768] + bias -> out
    gemm_kernel<128,128,16,8,8,false,true>
        <<<dim3(CC/128, MTOK/128, 1), 256>>>(
            attn, Wout, bout, out,
            MTOK, CC, CC,
            CC, CC, CC,
            1, 0,0, 0,0, 0,0, 1.0f);
}

// round 6
// speedup vs baseline: 2.6039x; 2.6039x over previous
#include <cuda_runtime.h>
#include <cstdint>
#include <math.h>

#define BB      16
#define NSEQ    1024
#define CC      768
#define HH      12
#define HDD     64
#define MTOK    (BB * NSEQ)      // 16384
#define QKVN    (3 * CC)         // 2304

// Scratch (static device globals; no runtime allocation)
__device__ float g_qkv[(size_t)MTOK * QKVN];
__device__ float g_scores[(size_t)BB * HH * NSEQ * NSEQ];
__device__ float g_attn[(size_t)MTOK * CC];

__device__ __forceinline__ uint32_t f2tf(float f) {
    uint32_t r;
    asm("cvt.rna.tf32.f32 %0, %1;" : "=r"(r) : "f"(f));
    return r;
}

// ---------------------------------------------------------------------------
// tf32 mma.sync GEMM (warp-level tensor cores; works on plain sm_103 target).
//   C = alpha * A * op(B) (+ bias), fp32 in/out, tf32 MMA fp32 accum.
//   op(B)=B    if !TRANSB (B is [K,Nn] row-major, ldb)
//   op(B)=B^T  if  TRANSB (B is [Nn,K] row-major, ldb)
// Block tile 128 x BN x 32, 256 threads (8 warps).
// Warp layout: WARPS_N = BN/32 cols, WARPS_M = 8/WARPS_N rows.
// All dims divide tiles exactly (true for every use here).
// ---------------------------------------------------------------------------
template<int BN, bool TRANSB, bool BIAS>
__global__ void __launch_bounds__(256)
mma_gemm(const float* __restrict__ A, const float* __restrict__ B,
         const float* __restrict__ bias, float* __restrict__ C,
         int K, int lda, int ldb, int ldc, int binner,
         long long sAo, long long sAi, long long sBo, long long sBi,
         long long sCo, long long sCi, float alpha)
{
    constexpr int BM = 128, BK = 32, PAD = 4;
    constexpr int WARPS_N = BN / 32;          // 4 (BN=128) or 2 (BN=64)
    constexpr int WARPS_M = 8 / WARPS_N;      // 2 or 4
    constexpr int WM = BM / WARPS_M;          // 64 or 32
    constexpr int WN = 32;
    constexpr int MITER = WM / 16;            // 4 or 2
    constexpr int NITER = WN / 8;             // 4
    constexpr int BSZ = TRANSB ? BN * (BK + PAD) : BK * (BN + PAD);

    __shared__ float As[BM][BK + PAD];
    __shared__ float Bs[BSZ];

    const int tid  = threadIdx.x;
    const int wid  = tid >> 5;
    const int lane = tid & 31;
    const int g    = lane >> 2;      // groupID (0..7)
    const int t    = lane & 3;       // thread-in-group (0..3)

    const int z  = blockIdx.z;
    const int zo = z / binner;
    const int zi = z % binner;
    A += zo * sAo + zi * sAi;
    B += zo * sBo + zi * sBi;
    C += zo * sCo + zi * sCi;

    const int bn0 = blockIdx.x * BN;
    const int bm0 = blockIdx.y * BM;
    const int wm0 = (wid / WARPS_N) * WM;
    const int wn0 = (wid % WARPS_N) * WN;

    float acc[MITER][NITER][4];
#pragma unroll
    for (int mi = 0; mi < MITER; mi++)
#pragma unroll
        for (int ni = 0; ni < NITER; ni++)
#pragma unroll
            for (int q = 0; q < 4; q++)
                acc[mi][ni][q] = 0.0f;

    for (int k0 = 0; k0 < K; k0 += BK) {
        // ---- A tile: [BM][BK], coalesced LDG, conflict-free STS
#pragma unroll
        for (int it = 0; it < (BM * BK) / 256; it++) {
            int idx = tid + it * 256;
            int r = idx >> 5, c = idx & 31;
            As[r][c] = A[(size_t)(bm0 + r) * lda + k0 + c];
        }
        // ---- B tile
        if (TRANSB) {   // B [Nn,K]: Bs[n][k]
#pragma unroll
            for (int it = 0; it < (BN * BK) / 256; it++) {
                int idx = tid + it * 256;
                int n = idx >> 5, c = idx & 31;
                Bs[n * (BK + PAD) + c] = B[(size_t)(bn0 + n) * ldb + k0 + c];
            }
        } else {        // B [K,Nn]: Bs[k][n]
#pragma unroll
            for (int it = 0; it < (BK * BN) / 256; it++) {
                int idx = tid + it * 256;
                int k = idx / BN, n = idx % BN;
                Bs[k * (BN + PAD) + n] = B[(size_t)(k0 + k) * ldb + bn0 + n];
            }
        }
        __syncthreads();

#pragma unroll
        for (int kk = 0; kk < BK; kk += 8) {
            uint32_t af[MITER][4];
#pragma unroll
            for (int mi = 0; mi < MITER; mi++) {
                int r0 = wm0 + mi * 16 + g;
                af[mi][0] = f2tf(As[r0    ][kk + t    ]);
                af[mi][1] = f2tf(As[r0 + 8][kk + t    ]);
                af[mi][2] = f2tf(As[r0    ][kk + t + 4]);
                af[mi][3] = f2tf(As[r0 + 8][kk + t + 4]);
            }
            uint32_t bf[NITER][2];
#pragma unroll
            for (int ni = 0; ni < NITER; ni++) {
                int n = wn0 + ni * 8 + g;
                if (TRANSB) {
                    bf[ni][0] = f2tf(Bs[n * (BK + PAD) + kk + t    ]);
                    bf[ni][1] = f2tf(Bs[n * (BK + PAD) + kk + t + 4]);
                } else {
                    bf[ni][0] = f2tf(Bs[(kk + t    ) * (BN + PAD) + n]);
                    bf[ni][1] = f2tf(Bs[(kk + t + 4) * (BN + PAD) + n]);
                }
            }
#pragma unroll
            for (int mi = 0; mi < MITER; mi++)
#pragma unroll
                for (int ni = 0; ni < NITER; ni++) {
                    asm volatile(
                        "mma.sync.aligned.m16n8k8.row.col.f32.tf32.tf32.f32 "
                        "{%0,%1,%2,%3}, {%4,%5,%6,%7}, {%8,%9}, {%0,%1,%2,%3};"
                        : "+f"(acc[mi][ni][0]), "+f"(acc[mi][ni][1]),
                          "+f"(acc[mi][ni][2]), "+f"(acc[mi][ni][3])
                        : "r"(af[mi][0]), "r"(af[mi][1]),
                          "r"(af[mi][2]), "r"(af[mi][3]),
                          "r"(bf[ni][0]), "r"(bf[ni][1]));
                }
        }
        __syncthreads();
    }

    // ---- epilogue: c0,c1 at (r0, 2t..2t+1), c2,c3 at (r0+8, same cols)
#pragma unroll
    for (int mi = 0; mi < MITER; mi++) {
#pragma unroll
        for (int ni = 0; ni < NITER; ni++) {
            int r0 = bm0 + wm0 + mi * 16 + g;
            int cn = bn0 + wn0 + ni * 8 + 2 * t;
            float bx = 0.f, by = 0.f;
            if (BIAS) { bx = bias[cn]; by = bias[cn + 1]; }
            float2 v01, v23;
            v01.x = acc[mi][ni][0] * alpha + bx;
            v01.y = acc[mi][ni][1] * alpha + by;
            v23.x = acc[mi][ni][2] * alpha + bx;
            v23.y = acc[mi][ni][3] * alpha + by;
            *(float2*)(C + (size_t)r0 * ldc + cn) = v01;
            *(float2*)(C + (size_t)(r0 + 8) * ldc + cn) = v23;
        }
    }
}

// ---------------------------------------------------------------------------
// Row softmax (rows of 1024), float4 I/O. One block = one row, 256 threads.
// ---------------------------------------------------------------------------
__global__ void softmax_kernel(float* __restrict__ S)
{
    float4* row = (float4*)(S + (size_t)blockIdx.x * NSEQ);
    const int tid = threadIdx.x;
    const int lane = tid & 31, w = tid >> 5;

    float4 v = row[tid];
    float m = fmaxf(fmaxf(v.x, v.y), fmaxf(v.z, v.w));
#pragma unroll
    for (int o = 16; o > 0; o >>= 1)
        m = fmaxf(m, __shfl_xor_sync(0xffffffffu, m, o));

    __shared__ float sm[8], ss[8];
    if (lane == 0) sm[w] = m;
    __syncthreads();
    m = sm[0];
#pragma unroll
    for (int i = 1; i < 8; i++) m = fmaxf(m, sm[i]);

    v.x = __expf(v.x - m); v.y = __expf(v.y - m);
    v.z = __expf(v.z - m); v.w = __expf(v.w - m);
    float s = v.x + v.y + v.z + v.w;
#pragma unroll
    for (int o = 16; o > 0; o >>= 1)
        s += __shfl_xor_sync(0xffffffffu, s, o);
    if (lane == 0) ss[w] = s;
    __syncthreads();
    float tot = 0.0f;
#pragma unroll
    for (int i = 0; i < 8; i++) tot += ss[i];

    float inv = 1.0f / tot;
    v.x *= inv; v.y *= inv; v.z *= inv; v.w *= inv;
    row[tid] = v;
}

// ---------------------------------------------------------------------------
// Launch
// ---------------------------------------------------------------------------
extern "C" void kernel_launch(void* const* d_in, const int* in_sizes, int n_in,
                              void* d_out, int out_size)
{
    const float* x    = (const float*)d_in[0];   // [B,N,C]
    const float* Wqkv = (const float*)d_in[1];   // [C, 3C]
    const float* bqkv = (const float*)d_in[2];   // [3C]
    const float* Wout = (const float*)d_in[3];   // [C, C]
    const float* bout = (const float*)d_in[4];   // [C]
    float* out = (float*)d_out;                  // [B,N,C]

    float *qkv = nullptr, *scores = nullptr, *attn = nullptr;
    cudaGetSymbolAddress((void**)&qkv,    g_qkv);
    cudaGetSymbolAddress((void**)&scores, g_scores);
    cudaGetSymbolAddress((void**)&attn,   g_attn);

    // 1) QKV projection: [16384,768] @ [768,2304] + bias
    mma_gemm<128, false, true><<<dim3(QKVN / 128, MTOK / 128, 1), 256>>>(
        x, Wqkv, bqkv, qkv,
        CC, CC, QKVN, QKVN,
        1, 0, 0, 0, 0, 0, 0, 1.0f);

    // 2) scores[b,h] = (Q K^T)/8 : 1024x1024x64, 192 batches (B=[N,K] direct)
    mma_gemm<128, true, false><<<dim3(NSEQ / 128, NSEQ / 128, BB * HH), 256>>>(
        qkv, qkv + CC, nullptr, scores,
        HDD, QKVN, QKVN, NSEQ,
        HH,
        (long long)NSEQ * QKVN, (long long)HDD,
        (long long)NSEQ * QKVN, (long long)HDD,
        (long long)HH * NSEQ * NSEQ, (long long)NSEQ * NSEQ,
        0.125f);

    // 3) softmax
    softmax_kernel<<<BB * HH * NSEQ, 256>>>(scores);

    // 4) attn[b,h] = P @ V : 1024x64x1024, 192 batches
    mma_gemm<64, false, false><<<dim3(1, NSEQ / 128, BB * HH), 256>>>(
        scores, qkv + 2 * CC, nullptr, attn,
        NSEQ, NSEQ, QKVN, CC,
        HH,
        (long long)HH * NSEQ * NSEQ, (long long)NSEQ * NSEQ,
        (long long)NSEQ * QKVN, (long long)HDD,
        (long long)NSEQ * CC, (long long)HDD,
        1.0f);

    // 5) output projection: [16384,768] @ [768,768] + bias
    mma_gemm<128, false, true><<<dim3(CC / 128, MTOK / 128, 1), 256>>>(
        attn, Wout, bout, out,
        CC, CC, CC, CC,
        1, 0, 0, 0, 0, 0, 0, 1.0f);
}